// round 2
// baseline (speedup 1.0000x reference)
#include <cuda_runtime.h>

#define N_ROWS 8192
#define D_DIM  1024
#define NUM_PAIRS 1024
#define MARGIN 0.05f
#define RPB 16   // rows per block in k_sim

__device__ float g_inv_tp, g_inv_tn;
__device__ float g_sp[N_ROWS], g_sn[N_ROWS];

// ---------------------------------------------------------------------------
// Kernel 0: inverse norms of the two text vectors. 1 block x 256 threads.
// ---------------------------------------------------------------------------
__global__ void k_textnorm(const float* __restrict__ tp, const float* __restrict__ tn) {
    __shared__ float sh[16];
    int t = threadIdx.x;                    // 256 threads, D=1024 -> float4 each
    float4 a = ((const float4*)tp)[t];
    float4 b = ((const float4*)tn)[t];
    float sa = a.x*a.x + a.y*a.y + a.z*a.z + a.w*a.w;
    float sb = b.x*b.x + b.y*b.y + b.z*b.z + b.w*b.w;
    #pragma unroll
    for (int o = 16; o > 0; o >>= 1) {
        sa += __shfl_xor_sync(0xffffffffu, sa, o);
        sb += __shfl_xor_sync(0xffffffffu, sb, o);
    }
    int wid = t >> 5, lane = t & 31;
    if (lane == 0) { sh[wid] = sa; sh[8 + wid] = sb; }
    __syncthreads();
    if (t == 0) {
        float A = 0.f, B = 0.f;
        #pragma unroll
        for (int i = 0; i < 8; i++) { A += sh[i]; B += sh[8 + i]; }
        g_inv_tp = rsqrtf(A);
        g_inv_tn = rsqrtf(B);
    }
}

// ---------------------------------------------------------------------------
// Kernel 1: per-row sims. 512 blocks x 256 threads, 16 rows per block.
// Each thread caches its float4 of tp/tn in registers across the 16 rows.
// ---------------------------------------------------------------------------
__global__ void k_sim(const float* __restrict__ X,
                      const float* __restrict__ tp,
                      const float* __restrict__ tn) {
    __shared__ float sh[24];
    int t = threadIdx.x;
    int wid = t >> 5, lane = t & 31;
    float4 p = ((const float4*)tp)[t];
    float4 q = ((const float4*)tn)[t];
    float itp = g_inv_tp, itn = g_inv_tn;
    int row0 = blockIdx.x * RPB;
    for (int r = 0; r < RPB; r++) {
        int row = row0 + r;
        float4 x = ((const float4*)(X + (size_t)row * D_DIM))[t];
        float dp = x.x*p.x + x.y*p.y + x.z*p.z + x.w*p.w;
        float dq = x.x*q.x + x.y*q.y + x.z*q.z + x.w*q.w;
        float dx = x.x*x.x + x.y*x.y + x.z*x.z + x.w*x.w;
        #pragma unroll
        for (int o = 16; o > 0; o >>= 1) {
            dp += __shfl_xor_sync(0xffffffffu, dp, o);
            dq += __shfl_xor_sync(0xffffffffu, dq, o);
            dx += __shfl_xor_sync(0xffffffffu, dx, o);
        }
        if (lane == 0) { sh[wid] = dp; sh[8 + wid] = dq; sh[16 + wid] = dx; }
        __syncthreads();
        if (t == 0) {
            float P = 0.f, Q = 0.f, XX = 0.f;
            #pragma unroll
            for (int i = 0; i < 8; i++) { P += sh[i]; Q += sh[8 + i]; XX += sh[16 + i]; }
            float inv = rsqrtf(XX);
            g_sp[row] = P * inv * itp;
            g_sn[row] = Q * inv * itn;
        }
        __syncthreads();
    }
}

// ---------------------------------------------------------------------------
// Kernel 2: counting sort by pair id in shared memory, then per-group
// triangular pair loop. 1 block x 1024 threads, ~82 KB dynamic smem.
// Shared layout:
//   ssp[8192] f32 | ssn[8192] f32 | s_start[1026] i32 | s_cnt[1024] i32 |
//   slev[8192] u8 | s_red[160] f32 | s_wsum[32] i32
// ---------------------------------------------------------------------------
#define SMEM_BYTES (N_ROWS*4 + N_ROWS*4 + 1026*4 + NUM_PAIRS*4 + N_ROWS + 160*4 + 32*4)

extern __shared__ unsigned char smem[];

__global__ void k_loss(const int* __restrict__ lev,
                       const int* __restrict__ pair,
                       float* __restrict__ out) {
    float* ssp     = (float*)smem;
    float* ssn     = ssp + N_ROWS;
    int*   s_start = (int*)(ssn + N_ROWS);          // 1026 ints (1025 used)
    int*   s_cnt   = s_start + 1026;                // counts, reused as cursor
    unsigned char* slev = (unsigned char*)(s_cnt + NUM_PAIRS);
    float* s_red   = (float*)(slev + N_ROWS);       // 5 x 32
    int*   s_wsum  = (int*)(s_red + 5 * 32);        // 32

    int tid  = threadIdx.x;          // 1024 threads
    int lane = tid & 31, wid = tid >> 5;

    // ---- count pass ----
    s_cnt[tid] = 0;
    __syncthreads();
    for (int i = tid; i < N_ROWS; i += 1024)
        atomicAdd(&s_cnt[pair[i]], 1);
    __syncthreads();

    // ---- exclusive scan of 1024 counts (warp scan + warp-sum scan) ----
    int v = s_cnt[tid];
    int inc = v;
    #pragma unroll
    for (int o = 1; o < 32; o <<= 1) {
        int nv = __shfl_up_sync(0xffffffffu, inc, o);
        if (lane >= o) inc += nv;
    }
    if (lane == 31) s_wsum[wid] = inc;
    __syncthreads();
    if (wid == 0) {
        int w  = s_wsum[lane];
        int wi = w;
        #pragma unroll
        for (int o = 1; o < 32; o <<= 1) {
            int nv = __shfl_up_sync(0xffffffffu, wi, o);
            if (lane >= o) wi += nv;
        }
        s_wsum[lane] = wi - w;   // exclusive warp prefix
    }
    __syncthreads();
    int excl = inc - v + s_wsum[wid];
    s_start[tid] = excl;
    if (tid == 1023) s_start[1024] = excl + v;
    __syncthreads();
    s_cnt[tid] = excl;           // cursor = start offset
    __syncthreads();

    // ---- scatter sims + levels into pair-sorted shared arrays ----
    for (int i = tid; i < N_ROWS; i += 1024) {
        int p   = pair[i];
        int pos = atomicAdd(&s_cnt[p], 1);
        ssp[pos]  = g_sp[i];
        ssn[pos]  = g_sn[i];
        slev[pos] = (unsigned char)lev[i];
    }
    __syncthreads();

    // ---- per-group triangular pair loop (thread g handles pair id g) ----
    float csum = 0.f, psum = 0.f, nsum = 0.f;
    int   ccnt = 0,  rcnt = 0;
    int s = s_start[tid], e = s_start[tid + 1];
    for (int a = s; a < e; a++) {
        float spa = ssp[a], sna = ssn[a];
        int   la  = slev[a];
        for (int b = a + 1; b < e; b++) {
            int   lb  = slev[b];
            float dsp = spa - ssp[b];
            float dsn = sna - ssn[b];
            if (la == lb) {
                // consistency: each unordered equal-level pair once (== upper triangle)
                csum += fabsf(dsp) + fabsf(dsn);
                ccnt++;
            } else {
                // rank: exactly one ordering has lev_i < lev_j
                float sgn = (la < lb) ? 1.f : -1.f;
                psum += fmaxf(MARGIN - sgn * dsp, 0.f);
                nsum += fmaxf(MARGIN + sgn * dsn, 0.f);
                rcnt++;
            }
        }
    }

    // ---- block reduction of 5 accumulators ----
    float fc = (float)ccnt, fr = (float)rcnt;
    #pragma unroll
    for (int o = 16; o > 0; o >>= 1) {
        csum += __shfl_xor_sync(0xffffffffu, csum, o);
        psum += __shfl_xor_sync(0xffffffffu, psum, o);
        nsum += __shfl_xor_sync(0xffffffffu, nsum, o);
        fc   += __shfl_xor_sync(0xffffffffu, fc,   o);
        fr   += __shfl_xor_sync(0xffffffffu, fr,   o);
    }
    if (lane == 0) {
        s_red[wid]       = csum;
        s_red[32  + wid] = psum;
        s_red[64  + wid] = nsum;
        s_red[96  + wid] = fc;
        s_red[128 + wid] = fr;
    }
    __syncthreads();
    if (tid == 0) {
        float C = 0.f, P = 0.f, Q = 0.f, FC = 0.f, FR = 0.f;
        for (int i = 0; i < 32; i++) {
            C  += s_red[i];
            P  += s_red[32 + i];
            Q  += s_red[64 + i];
            FC += s_red[96 + i];
            FR += s_red[128 + i];
        }
        float loss = 0.f;
        if (FC > 0.f) loss += C / fmaxf(2.f * FC, 1.f);
        if (FR > 0.f) loss += (P + Q) / FR;   // loss_pos + loss_neg, same mask/count
        out[0] = loss;
    }
}

// ---------------------------------------------------------------------------
// Launch: inputs in metadata order:
//   0 image_features f32[8192*1024], 1 text_features_pos f32[1024],
//   2 text_features_neg f32[1024],   3 degradation_levels i32[8192],
//   4 pair_indices i32[8192]         -> out f32[1]
// ---------------------------------------------------------------------------
extern "C" void kernel_launch(void* const* d_in, const int* in_sizes, int n_in,
                              void* d_out, int out_size) {
    const float* X   = (const float*)d_in[0];
    const float* tp  = (const float*)d_in[1];
    const float* tn  = (const float*)d_in[2];
    const int*   lev = (const int*)d_in[3];
    const int*   pr  = (const int*)d_in[4];
    float* out = (float*)d_out;

    cudaFuncSetAttribute(k_loss, cudaFuncAttributeMaxDynamicSharedMemorySize, SMEM_BYTES);

    k_textnorm<<<1, 256>>>(tp, tn);
    k_sim<<<N_ROWS / RPB, 256>>>(X, tp, tn);
    k_loss<<<1, 1024, SMEM_BYTES>>>(lev, pr, out);
}

// round 3
// speedup vs baseline: 1.0098x; 1.0098x over previous
#include <cuda_runtime.h>

#define N_ROWS 8192
#define D_DIM  1024
#define NUM_PAIRS 1024
#define MARGIN 0.05f
#define RPB 16   // rows per block in k_sim

__device__ float g_inv_tp, g_inv_tn;
__device__ float g_sp[N_ROWS], g_sn[N_ROWS];

// ---------------------------------------------------------------------------
// Kernel 0: inverse norms of the two text vectors. 1 block x 256 threads.
// ---------------------------------------------------------------------------
__global__ void k_textnorm(const float* __restrict__ tp, const float* __restrict__ tn) {
    __shared__ float sh[16];
    int t = threadIdx.x;                    // 256 threads, D=1024 -> float4 each
    float4 a = ((const float4*)tp)[t];
    float4 b = ((const float4*)tn)[t];
    float sa = a.x*a.x + a.y*a.y + a.z*a.z + a.w*a.w;
    float sb = b.x*b.x + b.y*b.y + b.z*b.z + b.w*b.w;
    #pragma unroll
    for (int o = 16; o > 0; o >>= 1) {
        sa += __shfl_xor_sync(0xffffffffu, sa, o);
        sb += __shfl_xor_sync(0xffffffffu, sb, o);
    }
    int wid = t >> 5, lane = t & 31;
    if (lane == 0) { sh[wid] = sa; sh[8 + wid] = sb; }
    __syncthreads();
    if (t == 0) {
        float A = 0.f, B = 0.f;
        #pragma unroll
        for (int i = 0; i < 8; i++) { A += sh[i]; B += sh[8 + i]; }
        g_inv_tp = rsqrtf(A);
        g_inv_tn = rsqrtf(B);
    }
}

// ---------------------------------------------------------------------------
// Kernel 1: per-row sims. 512 blocks x 256 threads, 16 rows per block.
// Each thread caches its float4 of tp/tn in registers across the 16 rows.
// ---------------------------------------------------------------------------
__global__ void k_sim(const float* __restrict__ X,
                      const float* __restrict__ tp,
                      const float* __restrict__ tn) {
    __shared__ float sh[24];
    int t = threadIdx.x;
    int wid = t >> 5, lane = t & 31;
    float4 p = ((const float4*)tp)[t];
    float4 q = ((const float4*)tn)[t];
    float itp = g_inv_tp, itn = g_inv_tn;
    int row0 = blockIdx.x * RPB;
    for (int r = 0; r < RPB; r++) {
        int row = row0 + r;
        float4 x = ((const float4*)(X + (size_t)row * D_DIM))[t];
        float dp = x.x*p.x + x.y*p.y + x.z*p.z + x.w*p.w;
        float dq = x.x*q.x + x.y*q.y + x.z*q.z + x.w*q.w;
        float dx = x.x*x.x + x.y*x.y + x.z*x.z + x.w*x.w;
        #pragma unroll
        for (int o = 16; o > 0; o >>= 1) {
            dp += __shfl_xor_sync(0xffffffffu, dp, o);
            dq += __shfl_xor_sync(0xffffffffu, dq, o);
            dx += __shfl_xor_sync(0xffffffffu, dx, o);
        }
        if (lane == 0) { sh[wid] = dp; sh[8 + wid] = dq; sh[16 + wid] = dx; }
        __syncthreads();
        if (t == 0) {
            float P = 0.f, Q = 0.f, XX = 0.f;
            #pragma unroll
            for (int i = 0; i < 8; i++) { P += sh[i]; Q += sh[8 + i]; XX += sh[16 + i]; }
            float inv = rsqrtf(XX);
            g_sp[row] = P * inv * itp;
            g_sn[row] = Q * inv * itn;
        }
        __syncthreads();
    }
}

// ---------------------------------------------------------------------------
// Kernel 2: counting sort by pair id in shared memory, then per-group
// triangular pair loop. 1 block x 1024 threads, ~82 KB dynamic smem.
// Shared layout:
//   ssp[8192] f32 | ssn[8192] f32 | s_start[1026] i32 | s_cnt[1024] i32 |
//   slev[8192] u8 | s_red[160] f32 | s_wsum[32] i32
// ---------------------------------------------------------------------------
#define SMEM_BYTES (N_ROWS*4 + N_ROWS*4 + 1026*4 + NUM_PAIRS*4 + N_ROWS + 160*4 + 32*4)

extern __shared__ unsigned char smem[];

__global__ void k_loss(const int* __restrict__ lev,
                       const int* __restrict__ pair,
                       float* __restrict__ out) {
    float* ssp     = (float*)smem;
    float* ssn     = ssp + N_ROWS;
    int*   s_start = (int*)(ssn + N_ROWS);          // 1026 ints (1025 used)
    int*   s_cnt   = s_start + 1026;                // counts, reused as cursor
    unsigned char* slev = (unsigned char*)(s_cnt + NUM_PAIRS);
    float* s_red   = (float*)(slev + N_ROWS);       // 5 x 32
    int*   s_wsum  = (int*)(s_red + 5 * 32);        // 32

    int tid  = threadIdx.x;          // 1024 threads
    int lane = tid & 31, wid = tid >> 5;

    // ---- count pass ----
    s_cnt[tid] = 0;
    __syncthreads();
    for (int i = tid; i < N_ROWS; i += 1024)
        atomicAdd(&s_cnt[pair[i]], 1);
    __syncthreads();

    // ---- exclusive scan of 1024 counts (warp scan + warp-sum scan) ----
    int v = s_cnt[tid];
    int inc = v;
    #pragma unroll
    for (int o = 1; o < 32; o <<= 1) {
        int nv = __shfl_up_sync(0xffffffffu, inc, o);
        if (lane >= o) inc += nv;
    }
    if (lane == 31) s_wsum[wid] = inc;
    __syncthreads();
    if (wid == 0) {
        int w  = s_wsum[lane];
        int wi = w;
        #pragma unroll
        for (int o = 1; o < 32; o <<= 1) {
            int nv = __shfl_up_sync(0xffffffffu, wi, o);
            if (lane >= o) wi += nv;
        }
        s_wsum[lane] = wi - w;   // exclusive warp prefix
    }
    __syncthreads();
    int excl = inc - v + s_wsum[wid];
    s_start[tid] = excl;
    if (tid == 1023) s_start[1024] = excl + v;
    __syncthreads();
    s_cnt[tid] = excl;           // cursor = start offset
    __syncthreads();

    // ---- scatter sims + levels into pair-sorted shared arrays ----
    for (int i = tid; i < N_ROWS; i += 1024) {
        int p   = pair[i];
        int pos = atomicAdd(&s_cnt[p], 1);
        ssp[pos]  = g_sp[i];
        ssn[pos]  = g_sn[i];
        slev[pos] = (unsigned char)lev[i];
    }
    __syncthreads();

    // ---- per-group triangular pair loop (thread g handles pair id g) ----
    float csum = 0.f, psum = 0.f, nsum = 0.f;
    int   ccnt = 0,  rcnt = 0;
    int s = s_start[tid], e = s_start[tid + 1];
    for (int a = s; a < e; a++) {
        float spa = ssp[a], sna = ssn[a];
        int   la  = slev[a];
        for (int b = a + 1; b < e; b++) {
            int   lb  = slev[b];
            float dsp = spa - ssp[b];
            float dsn = sna - ssn[b];
            if (la == lb) {
                // consistency: each unordered equal-level pair once (== upper triangle)
                csum += fabsf(dsp) + fabsf(dsn);
                ccnt++;
            } else {
                // rank: exactly one ordering has lev_i < lev_j
                float sgn = (la < lb) ? 1.f : -1.f;
                psum += fmaxf(MARGIN - sgn * dsp, 0.f);
                nsum += fmaxf(MARGIN + sgn * dsn, 0.f);
                rcnt++;
            }
        }
    }

    // ---- block reduction of 5 accumulators ----
    float fc = (float)ccnt, fr = (float)rcnt;
    #pragma unroll
    for (int o = 16; o > 0; o >>= 1) {
        csum += __shfl_xor_sync(0xffffffffu, csum, o);
        psum += __shfl_xor_sync(0xffffffffu, psum, o);
        nsum += __shfl_xor_sync(0xffffffffu, nsum, o);
        fc   += __shfl_xor_sync(0xffffffffu, fc,   o);
        fr   += __shfl_xor_sync(0xffffffffu, fr,   o);
    }
    if (lane == 0) {
        s_red[wid]       = csum;
        s_red[32  + wid] = psum;
        s_red[64  + wid] = nsum;
        s_red[96  + wid] = fc;
        s_red[128 + wid] = fr;
    }
    __syncthreads();
    if (tid == 0) {
        float C = 0.f, P = 0.f, Q = 0.f, FC = 0.f, FR = 0.f;
        for (int i = 0; i < 32; i++) {
            C  += s_red[i];
            P  += s_red[32 + i];
            Q  += s_red[64 + i];
            FC += s_red[96 + i];
            FR += s_red[128 + i];
        }
        float loss = 0.f;
        if (FC > 0.f) loss += C / fmaxf(2.f * FC, 1.f);
        if (FR > 0.f) loss += (P + Q) / FR;   // loss_pos + loss_neg, same mask/count
        out[0] = loss;
    }
}

// ---------------------------------------------------------------------------
// Launch: inputs in metadata order:
//   0 image_features f32[8192*1024], 1 text_features_pos f32[1024],
//   2 text_features_neg f32[1024],   3 degradation_levels i32[8192],
//   4 pair_indices i32[8192]         -> out f32[1]
// ---------------------------------------------------------------------------
extern "C" void kernel_launch(void* const* d_in, const int* in_sizes, int n_in,
                              void* d_out, int out_size) {
    const float* X   = (const float*)d_in[0];
    const float* tp  = (const float*)d_in[1];
    const float* tn  = (const float*)d_in[2];
    const int*   lev = (const int*)d_in[3];
    const int*   pr  = (const int*)d_in[4];
    float* out = (float*)d_out;

    cudaFuncSetAttribute(k_loss, cudaFuncAttributeMaxDynamicSharedMemorySize, SMEM_BYTES);

    k_textnorm<<<1, 256>>>(tp, tn);
    k_sim<<<N_ROWS / RPB, 256>>>(X, tp, tn);
    k_loss<<<1, 1024, SMEM_BYTES>>>(lev, pr, out);
}